// round 15
// baseline (speedup 1.0000x reference)
#include <cuda_runtime.h>
#include <cstdint>

#define NN     20000
#define KO     32
#define MTILE  64
#define KTILE  32
#define KT_PER 625            // k-tiles per m-tile
#define NMT    313            // ceil(20000/64)
#define TT     (NMT * KT_PER) // 195625 global tiles
#define GRIDP  740            // one exact wave
#define NPLANE 4              // max segments per m-tile
#define SBLK   157

#define APADF  40                      // A smem row stride (floats): LDS.64 bank-perfect
#define A_BYTES (MTILE * APADF * 4)    // 10240
#define XPL_B   2048                   // one X plane: 16 kpairs x 32 bf16x2
#define STAGEB  (A_BYTES + 2 * XPL_B)  // 14336
#define NSTAGE  3
#define SMEM_TOTAL (STAGEB * NSTAGE)   // 43008 -> 5 CTAs/SM

// ---- scratch (no allocations allowed) ----
__device__ __align__(16) uint32_t g_Xb[2][(NN / 2) * KO];   // packed bf16x2 hi/lo planes
__device__ __align__(16) float g_Hp [NPLANE][NN * KO];
__device__ __align__(16) float g_H2 [NN * KO];
__device__ __align__(16) float g_part[SBLK * KO];
__device__ __align__(16) float g_psq [SBLK * KO];
__device__ float g_scale[KO];
__device__ float g_shift[KO];

// ================= helpers =================
__device__ __forceinline__ uint32_t smem_u32(const void* p) {
    uint32_t a;
    asm("{ .reg .u64 t; cvta.to.shared.u64 t, %1; cvt.u32.u64 %0, t; }" : "=r"(a) : "l"(p));
    return a;
}
__device__ __forceinline__ void cp16(uint32_t dst, const void* src, bool ok) {
    asm volatile("cp.async.cg.shared.global [%0], [%1], 16, %2;"
                 :: "r"(dst), "l"(src), "r"(ok ? 16u : 0u) : "memory");
}
#define CP_COMMIT() asm volatile("cp.async.commit_group;" ::: "memory")
#define CP_WAIT2()  asm volatile("cp.async.wait_group 2;" ::: "memory")
#define CP_WAIT0()  asm volatile("cp.async.wait_group 0;" ::: "memory")

__device__ __host__ __forceinline__ int cover_b(uint64_t tau) {
    return (int)(((tau + 1) * (uint64_t)GRIDP - 1) / (uint64_t)TT);
}

// split a k-adjacent fp32 pair into packed bf16x2 (hi via truncation, lo = exact residue truncated)
__device__ __forceinline__ void bsplit2(float x0, float x1, uint32_t& hi, uint32_t& lo) {
    uint32_t u0 = __float_as_uint(x0), u1 = __float_as_uint(x1);
    hi = __byte_perm(u0, u1, 0x7632);
    float l0 = x0 - __uint_as_float(u0 & 0xFFFF0000u);
    float l1 = x1 - __uint_as_float(u1 & 0xFFFF0000u);
    lo = __byte_perm(__float_as_uint(l0), __float_as_uint(l1), 0x7632);
}
__device__ __forceinline__ void mma16(float& c0, float& c1, float& c2, float& c3,
                                      uint32_t a0, uint32_t a1, uint32_t a2, uint32_t a3,
                                      uint32_t b0, uint32_t b1) {
    asm volatile(
        "mma.sync.aligned.m16n8k16.row.col.f32.bf16.bf16.f32 "
        "{%0,%1,%2,%3}, {%4,%5,%6,%7}, {%8,%9}, {%0,%1,%2,%3};"
        : "+f"(c0), "+f"(c1), "+f"(c2), "+f"(c3)
        : "r"(a0), "r"(a1), "r"(a2), "r"(a3), "r"(b0), "r"(b1));
}

// ============ Kernel 0: X -> packed bf16x2 hi/lo planes ============
__global__ void k_prep(const float* __restrict__ X) {
    int i = blockIdx.x * blockDim.x + threadIdx.x;   // < 320000
    int kp = i >> 5, n = i & 31;
    float x0 = X[(2 * kp) * KO + n];
    float x1 = X[(2 * kp + 1) * KO + n];
    uint32_t hi, lo;
    bsplit2(x0, x1, hi, lo);
    g_Xb[0][i] = hi;
    g_Xb[1][i] = lo;
}

// ====== Kernel 1: 740 balanced persistent CTAs, 3xBF16 k16, 2m x 2k warps ======
__global__ __launch_bounds__(128, 5)
void k_gemm1(const float* __restrict__ A) {
    extern __shared__ __align__(128) char sm[];
    const uint32_t smb = smem_u32(sm);
    const int tid  = threadIdx.x;
    const int wid  = tid >> 5;
    const int kw   = wid & 1;         // k-half: k16 slice [16*kw, 16*kw+16)
    const int mh   = wid >> 1;        // m-half: rows [32*mh, 32*mh+32)
    const int lane = tid & 31;
    const int g    = lane >> 2;       // 0..7
    const int tq   = lane & 3;        // 0..3
    const int b    = blockIdx.x;

    uint64_t tau = (uint64_t)b * TT / GRIDP;
    const uint64_t tend = (uint64_t)(b + 1) * TT / GRIDP;

    while (tau < tend) {
        const int mt  = (int)(tau / KT_PER);
        const int T0  = (int)(tau - (uint64_t)mt * KT_PER);
        uint64_t mend = (uint64_t)(mt + 1) * KT_PER;
        const int T1  = (tend < mend) ? (int)(tend - (uint64_t)mt * KT_PER) : KT_PER;
        const int ord = b - cover_b((uint64_t)mt * KT_PER);
        const size_t m0 = (size_t)mt * MTILE;

        auto load_stage = [&](int s, int t) {
            const uint32_t sb = smb + s * STAGEB;
            const int k0 = t * KTILE;
            // A: 64 rows x 8 c4 = 512 slots, 4/thread
#pragma unroll
            for (int v = 0; v < 4; v++) {
                int slot = tid + 128 * v;
                int r  = slot >> 3;
                int c4 = slot & 7;
                bool ok = (m0 + r) < NN;
                cp16(sb + (uint32_t)(r * APADF + c4 * 4) * 4,
                     A + (m0 + r) * NN + k0 + c4 * 4, ok);
            }
            // X planes: 2 x 16 rows x 8 c4 = 256 slots, 2/thread; XOR swizzle on 4-entry chunks
#pragma unroll
            for (int v = 0; v < 2; v++) {
                int slot = tid + 128 * v;          // 0..255
                int pl = slot >> 7;
                int rr = (slot >> 3) & 15;         // kpair row in tile
                int c4 = slot & 7;
                uint32_t ent = rr * 32 + ((c4 * 4) ^ (8 * (rr & 3)));
                cp16(sb + A_BYTES + pl * XPL_B + ent * 4,
                     g_Xb[pl] + (size_t)(16 * t + rr) * 32 + c4 * 4, true);
            }
            CP_COMMIT();
        };

        load_stage(0, T0);
        load_stage(1, min(T0 + 1, T1 - 1));
        load_stage(2, min(T0 + 2, T1 - 1));

        float acc[2][4][4];
#pragma unroll
        for (int mf = 0; mf < 2; mf++)
#pragma unroll
            for (int nt = 0; nt < 4; nt++)
#pragma unroll
                for (int v = 0; v < 4; v++) acc[mf][nt][v] = 0.f;

        for (int t = T0; t < T1; t++) {
            const int s = (t - T0) % NSTAGE;
            CP_WAIT2();
            __syncthreads();
            const float*    As = (const float*)(sm + s * STAGEB);
            const uint32_t* Xh = (const uint32_t*)(sm + s * STAGEB + A_BYTES);
            const uint32_t* Xl = Xh + 512;

            // X fragments: pre-packed bf16x2, zero ALU
            uint32_t bhi[4][2], blo[4][2];
            const int r0x = 8 * kw + tq;          // kpair row (b0)
            const int r1x = r0x + 4;              // (b1); (tq+4)&3 == tq -> same swizzle key
#pragma unroll
            for (int nt = 0; nt < 4; nt++) {
                int c = (8 * nt + g) ^ (8 * tq);
                bhi[nt][0] = Xh[r0x * 32 + c];
                bhi[nt][1] = Xh[r1x * 32 + c];
                blo[nt][0] = Xl[r0x * 32 + c];
                blo[nt][1] = Xl[r1x * 32 + c];
            }
            // A fragments: LDS.64 k-pairs, split+pack
            uint32_t ahi[2][4], alo[2][4];
            const int c0 = 16 * kw + 2 * tq;
#pragma unroll
            for (int mf = 0; mf < 2; mf++) {
                int rb = mh * 32 + mf * 16 + g;
                float2 p00 = *(const float2*)(As + rb * APADF + c0);
                float2 p10 = *(const float2*)(As + (rb + 8) * APADF + c0);
                float2 p01 = *(const float2*)(As + rb * APADF + c0 + 8);
                float2 p11 = *(const float2*)(As + (rb + 8) * APADF + c0 + 8);
                bsplit2(p00.x, p00.y, ahi[mf][0], alo[mf][0]);
                bsplit2(p10.x, p10.y, ahi[mf][1], alo[mf][1]);
                bsplit2(p01.x, p01.y, ahi[mf][2], alo[mf][2]);
                bsplit2(p11.x, p11.y, ahi[mf][3], alo[mf][3]);
            }
            // stage released: issue next load before compute
            __syncthreads();
            if (t + NSTAGE < T1) load_stage(s, t + NSTAGE);
            else CP_COMMIT();   // keep group count aligned

#pragma unroll
            for (int mf = 0; mf < 2; mf++)
#pragma unroll
                for (int nt = 0; nt < 4; nt++) {
                    mma16(acc[mf][nt][0], acc[mf][nt][1], acc[mf][nt][2], acc[mf][nt][3],
                          ahi[mf][0], ahi[mf][1], ahi[mf][2], ahi[mf][3],
                          bhi[nt][0], bhi[nt][1]);
                    mma16(acc[mf][nt][0], acc[mf][nt][1], acc[mf][nt][2], acc[mf][nt][3],
                          alo[mf][0], alo[mf][1], alo[mf][2], alo[mf][3],
                          bhi[nt][0], bhi[nt][1]);
                    mma16(acc[mf][nt][0], acc[mf][nt][1], acc[mf][nt][2], acc[mf][nt][3],
                          ahi[mf][0], ahi[mf][1], ahi[mf][2], ahi[mf][3],
                          blo[nt][0], blo[nt][1]);
                }
        }
        CP_WAIT0();

        // ---- segment epilogue: 2 k-warp partial planes -> fixed-order sum -> g_Hp[ord] ----
        __syncthreads();
        float* Hp = (float*)sm;                   // 2 * 64 * 33 * 4 = 16896 <= 43008
#pragma unroll
        for (int mf = 0; mf < 2; mf++) {
            int r0 = mh * 32 + mf * 16 + g;
#pragma unroll
            for (int nt = 0; nt < 4; nt++) {
                int cc = nt * 8 + 2 * tq;
                float* Hw = Hp + kw * MTILE * 33;
                Hw[r0 * 33 + cc]           = acc[mf][nt][0];
                Hw[r0 * 33 + cc + 1]       = acc[mf][nt][1];
                Hw[(r0 + 8) * 33 + cc]     = acc[mf][nt][2];
                Hw[(r0 + 8) * 33 + cc + 1] = acc[mf][nt][3];
            }
        }
        __syncthreads();

        if (tid < MTILE && (m0 + tid) < NN) {
            float h[32];
#pragma unroll
            for (int k = 0; k < 32; k++)          // deterministic: kw 0 then 1
                h[k] = Hp[tid * 33 + k] + Hp[MTILE * 33 + tid * 33 + k];
            float4* o = (float4*)(g_Hp[ord] + (m0 + tid) * KO);
#pragma unroll
            for (int n4 = 0; n4 < 8; n4++)
                o[n4] = make_float4(h[n4*4], h[n4*4+1], h[n4*4+2], h[n4*4+3]);
        }
        __syncthreads();   // smem free before next segment's loads

        tau = (uint64_t)mt * KT_PER + T1;
    }
}

// ====== Kernel 2: combine nseg planes, h2 = h @ W, BN partials (deterministic) ======
__global__ __launch_bounds__(128)
void k_combine(const float* __restrict__ W) {
    __shared__ float Ws[32 * 32];
    __shared__ float red[128 * 32];
    const int tid = threadIdx.x;
#pragma unroll
    for (int u = 0; u < 8; u++) Ws[tid + 128 * u] = W[tid + 128 * u];
    __syncthreads();

    const size_t row = (size_t)blockIdx.x * 128 + tid;
    float h2[32];
    if (row < NN) {
        const int mt = (int)(row / MTILE);
        const int bf = cover_b((uint64_t)mt * KT_PER);
        const int bl = cover_b((uint64_t)mt * KT_PER + KT_PER - 1);
        const int nseg = bl - bf + 1;              // <= NPLANE
        float h[32];
        {
            const float4* p = (const float4*)(g_Hp[0] + row * KO);
#pragma unroll
            for (int q = 0; q < 8; q++) {
                float4 a = p[q];
                h[q*4+0] = a.x; h[q*4+1] = a.y; h[q*4+2] = a.z; h[q*4+3] = a.w;
            }
        }
        for (int sgi = 1; sgi < nseg; sgi++) {     // fixed ord order
            const float4* p = (const float4*)(g_Hp[sgi] + row * KO);
#pragma unroll
            for (int q = 0; q < 8; q++) {
                float4 a = p[q];
                h[q*4+0] += a.x; h[q*4+1] += a.y; h[q*4+2] += a.z; h[q*4+3] += a.w;
            }
        }
#pragma unroll
        for (int n = 0; n < 32; n++) {
            float s = 0.f;
#pragma unroll
            for (int k = 0; k < 32; k++) s += h[k] * Ws[k * 32 + n];
            h2[n] = s;
        }
        float4* o = (float4*)(g_H2 + row * KO);
#pragma unroll
        for (int q = 0; q < 8; q++)
            o[q] = make_float4(h2[q*4], h2[q*4+1], h2[q*4+2], h2[q*4+3]);
    } else {
#pragma unroll
        for (int n = 0; n < 32; n++) h2[n] = 0.f;
    }

#pragma unroll
    for (int n = 0; n < 32; n++) red[tid * 32 + n] = h2[n];
    __syncthreads();
    for (int st = 64; st > 0; st >>= 1) {
        if (tid < st) {
#pragma unroll
            for (int n = 0; n < 32; n++)
                red[tid * 32 + n] += red[(tid + st) * 32 + n];
        }
        __syncthreads();
    }
    if (tid < 32) g_part[blockIdx.x * KO + tid] = red[tid];
    __syncthreads();
#pragma unroll
    for (int n = 0; n < 32; n++) red[tid * 32 + n] = h2[n] * h2[n];
    __syncthreads();
    for (int st = 64; st > 0; st >>= 1) {
        if (tid < st) {
#pragma unroll
            for (int n = 0; n < 32; n++)
                red[tid * 32 + n] += red[(tid + st) * 32 + n];
        }
        __syncthreads();
    }
    if (tid < 32) g_psq[blockIdx.x * KO + tid] = red[tid];
}

// ========== Kernel 3: finalize BN stats — warp per column, fixed shuffle tree ==========
__global__ void k_stats(const float* __restrict__ gamma,
                        const float* __restrict__ beta,
                        const float* __restrict__ bias) {
    const int c = threadIdx.x >> 5;   // warp = column 0..31
    const int l = threadIdx.x & 31;
    double s = 0.0, qq = 0.0;
    for (int b = l; b < SBLK; b += 32) {      // 5 independent loads per lane
        s  += (double)g_part[b * KO + c];
        qq += (double)g_psq [b * KO + c];
    }
#pragma unroll
    for (int off = 16; off > 0; off >>= 1) {  // deterministic fixed tree
        s  += __shfl_down_sync(0xFFFFFFFFu, s,  off);
        qq += __shfl_down_sync(0xFFFFFFFFu, qq, off);
    }
    if (l == 0) {
        double mean = s / (double)NN;
        double var  = qq / (double)NN - mean * mean;
        double inv  = 1.0 / sqrt(var + 1e-5);
        double gsc  = (double)gamma[c] * inv;
        g_scale[c] = (float)gsc;
        g_shift[c] = (float)((double)beta[c] + (double)bias[c] - mean * gsc);
    }
}

// ========== Kernel 4: out = relu(H2*scale + shift), 16 elems/thread ==========
__global__ void k_apply(float* __restrict__ out) {
    int i = blockIdx.x * blockDim.x + threadIdx.x;     // 0..39999 handle 4 float4 each
    if (i >= (NN * KO) / 16) return;
    const float4* hp = (const float4*)g_H2 + (size_t)i * 4;
    float4*       op = (float4*)out + (size_t)i * 4;
    const int cb = (i * 16) & 31;                       // 0 or 16
    float4 h0 = hp[0], h1 = hp[1], h2v = hp[2], h3 = hp[3];   // MLP = 4
#pragma unroll
    for (int q = 0; q < 4; q++) {
        float4 h = (q == 0) ? h0 : (q == 1) ? h1 : (q == 2) ? h2v : h3;
        float4 sc = *(const float4*)(g_scale + cb + 4 * q);
        float4 sh = *(const float4*)(g_shift + cb + 4 * q);
        float4 o;
        o.x = fmaxf(h.x * sc.x + sh.x, 0.f);
        o.y = fmaxf(h.y * sc.y + sh.y, 0.f);
        o.z = fmaxf(h.z * sc.z + sh.z, 0.f);
        o.w = fmaxf(h.w * sc.w + sh.w, 0.f);
        op[q] = o;
    }
}

// ================= launch =================
extern "C" void kernel_launch(void* const* d_in, const int* in_sizes, int n_in,
                              void* d_out, int out_size) {
    const float* A     = (const float*)d_in[0];
    const float* X     = (const float*)d_in[1];
    const float* W     = (const float*)d_in[2];
    const float* gamma = (const float*)d_in[3];
    const float* beta  = (const float*)d_in[4];
    const float* bias  = (const float*)d_in[5];
    float* out = (float*)d_out;

    cudaFuncSetAttribute(k_gemm1, cudaFuncAttributeMaxDynamicSharedMemorySize, SMEM_TOTAL);

    k_prep<<<(NN / 2) * KO / 256, 256>>>(X);
    k_gemm1<<<GRIDP, 128, SMEM_TOTAL>>>(A);
    k_combine<<<SBLK, 128>>>(W);
    k_stats<<<1, 1024>>>(gamma, beta, bias);
    k_apply<<<(NN * KO / 16 + 255) / 256, 256>>>(out);
}

// round 16
// speedup vs baseline: 1.1374x; 1.1374x over previous
#include <cuda_runtime.h>
#include <cstdint>

#define NN     20000
#define KO     32
#define MTILE  64
#define KTILE  32
#define KT_PER 625            // k-tiles per m-tile
#define NMT    313            // ceil(20000/64)
#define TT     (NMT * KT_PER) // 195625 global tiles
#define GRIDP  740            // one exact wave
#define NPLANE 4              // max segments per m-tile
#define SBLK   157

#define APADF  40                      // A smem row stride (floats): LDS.64 bank-perfect
#define A_BYTES (MTILE * APADF * 4)    // 10240
#define XPL_B   2048                   // one X plane: 16 kpairs x 32 bf16x2
#define STAGEB  (A_BYTES + 2 * XPL_B)  // 14336
#define NSTAGE  3
#define SMEM_TOTAL (STAGEB * NSTAGE)   // 43008 -> 5 CTAs/SM

// ---- scratch (no allocations allowed) ----
__device__ __align__(16) uint32_t g_Xb[2][(NN / 2) * KO];   // packed bf16x2 hi/lo planes
__device__ __align__(16) float g_Hp [NPLANE][NN * KO];
__device__ __align__(16) float g_H2 [NN * KO];
__device__ __align__(16) float g_part[SBLK * KO];
__device__ __align__(16) float g_psq [SBLK * KO];
__device__ float g_scale[KO];
__device__ float g_shift[KO];

// ================= helpers =================
__device__ __forceinline__ uint32_t smem_u32(const void* p) {
    uint32_t a;
    asm("{ .reg .u64 t; cvta.to.shared.u64 t, %1; cvt.u32.u64 %0, t; }" : "=r"(a) : "l"(p));
    return a;
}
__device__ __forceinline__ void cp16(uint32_t dst, const void* src, bool ok) {
    asm volatile("cp.async.cg.shared.global [%0], [%1], 16, %2;"
                 :: "r"(dst), "l"(src), "r"(ok ? 16u : 0u) : "memory");
}
#define CP_COMMIT() asm volatile("cp.async.commit_group;" ::: "memory")
#define CP_WAIT1()  asm volatile("cp.async.wait_group 1;" ::: "memory")
#define CP_WAIT0()  asm volatile("cp.async.wait_group 0;" ::: "memory")

__device__ __host__ __forceinline__ int cover_b(uint64_t tau) {
    return (int)(((tau + 1) * (uint64_t)GRIDP - 1) / (uint64_t)TT);
}

// split a k-adjacent fp32 pair into packed bf16x2 (hi via truncation, lo = exact residue truncated)
__device__ __forceinline__ void bsplit2(float x0, float x1, uint32_t& hi, uint32_t& lo) {
    uint32_t u0 = __float_as_uint(x0), u1 = __float_as_uint(x1);
    hi = __byte_perm(u0, u1, 0x7632);
    float l0 = x0 - __uint_as_float(u0 & 0xFFFF0000u);
    float l1 = x1 - __uint_as_float(u1 & 0xFFFF0000u);
    lo = __byte_perm(__float_as_uint(l0), __float_as_uint(l1), 0x7632);
}
__device__ __forceinline__ void mma16(float& c0, float& c1, float& c2, float& c3,
                                      uint32_t a0, uint32_t a1, uint32_t a2, uint32_t a3,
                                      uint32_t b0, uint32_t b1) {
    asm volatile(
        "mma.sync.aligned.m16n8k16.row.col.f32.bf16.bf16.f32 "
        "{%0,%1,%2,%3}, {%4,%5,%6,%7}, {%8,%9}, {%0,%1,%2,%3};"
        : "+f"(c0), "+f"(c1), "+f"(c2), "+f"(c3)
        : "r"(a0), "r"(a1), "r"(a2), "r"(a3), "r"(b0), "r"(b1));
}

// ============ Kernel 0: X -> packed bf16x2 hi/lo planes ============
__global__ void k_prep(const float* __restrict__ X) {
    int i = blockIdx.x * blockDim.x + threadIdx.x;   // < 320000
    int kp = i >> 5, n = i & 31;
    float x0 = X[(2 * kp) * KO + n];
    float x1 = X[(2 * kp + 1) * KO + n];
    uint32_t hi, lo;
    bsplit2(x0, x1, hi, lo);
    g_Xb[0][i] = hi;
    g_Xb[1][i] = lo;
}

// ====== Kernel 1: persistent balanced CTAs, 3xBF16 k16, ONE sync per tile ======
__global__ __launch_bounds__(128, 5)
void k_gemm1(const float* __restrict__ A) {
    extern __shared__ __align__(128) char sm[];
    const uint32_t smb = smem_u32(sm);
    const int tid  = threadIdx.x;
    const int wid  = tid >> 5;
    const int kw   = wid & 1;         // k-half: k16 slice [16*kw, 16*kw+16)
    const int mh   = wid >> 1;        // m-half: rows [32*mh, 32*mh+32)
    const int lane = tid & 31;
    const int g    = lane >> 2;       // 0..7
    const int tq   = lane & 3;        // 0..3
    const int b    = blockIdx.x;

    uint64_t tau = (uint64_t)b * TT / GRIDP;
    const uint64_t tend = (uint64_t)(b + 1) * TT / GRIDP;

    while (tau < tend) {
        const int mt  = (int)(tau / KT_PER);
        const int T0  = (int)(tau - (uint64_t)mt * KT_PER);
        uint64_t mend = (uint64_t)(mt + 1) * KT_PER;
        const int T1  = (tend < mend) ? (int)(tend - (uint64_t)mt * KT_PER) : KT_PER;
        const int ord = b - cover_b((uint64_t)mt * KT_PER);
        const size_t m0 = (size_t)mt * MTILE;

        auto load_stage = [&](int s, int t) {
            const uint32_t sb = smb + s * STAGEB;
            const int k0 = t * KTILE;
            // A: 64 rows x 8 c4 = 512 slots, 4/thread
#pragma unroll
            for (int v = 0; v < 4; v++) {
                int slot = tid + 128 * v;
                int r  = slot >> 3;
                int c4 = slot & 7;
                bool ok = (m0 + r) < NN;
                cp16(sb + (uint32_t)(r * APADF + c4 * 4) * 4,
                     A + (m0 + r) * NN + k0 + c4 * 4, ok);
            }
            // X planes: 2 x 16 rows x 8 c4 = 256 slots, 2/thread; XOR swizzle on 4-entry chunks
#pragma unroll
            for (int v = 0; v < 2; v++) {
                int slot = tid + 128 * v;          // 0..255
                int pl = slot >> 7;
                int rr = (slot >> 3) & 15;         // kpair row in tile
                int c4 = slot & 7;
                uint32_t ent = rr * 32 + ((c4 * 4) ^ (8 * (rr & 3)));
                cp16(sb + A_BYTES + pl * XPL_B + ent * 4,
                     g_Xb[pl] + (size_t)(16 * t + rr) * 32 + c4 * 4, true);
            }
            CP_COMMIT();
        };

        // prefetch distance 2: groups for T0, T0+1 in flight
        load_stage(T0 % NSTAGE, T0);
        if (T0 + 1 < T1) load_stage((T0 + 1) % NSTAGE, T0 + 1);
        else CP_COMMIT();

        float acc[2][4][4];
#pragma unroll
        for (int mf = 0; mf < 2; mf++)
#pragma unroll
            for (int nt = 0; nt < 4; nt++)
#pragma unroll
                for (int v = 0; v < 4; v++) acc[mf][nt][v] = 0.f;

        for (int t = T0; t < T1; t++) {
            const int s = t % NSTAGE;
            CP_WAIT1();                 // group(t) complete; group(t+1) may pend
            __syncthreads();            // all warps done with stage (t+2)%NSTAGE (read at t-1)

            // issue prefetch for t+2 FIRST (stage (t+2)%3 is free by the sync above)
            if (t + 2 < T1) load_stage((t + 2) % NSTAGE, t + 2);
            else CP_COMMIT();           // keep group count aligned

            const float*    As = (const float*)(sm + s * STAGEB);
            const uint32_t* Xh = (const uint32_t*)(sm + s * STAGEB + A_BYTES);
            const uint32_t* Xl = Xh + 512;

            // X fragments: pre-packed bf16x2, zero ALU
            uint32_t bhi[4][2], blo[4][2];
            const int r0x = 8 * kw + tq;          // kpair row (b0)
            const int r1x = r0x + 4;              // (b1); (tq+4)&3 == tq -> same swizzle key
#pragma unroll
            for (int nt = 0; nt < 4; nt++) {
                int c = (8 * nt + g) ^ (8 * tq);
                bhi[nt][0] = Xh[r0x * 32 + c];
                bhi[nt][1] = Xh[r1x * 32 + c];
                blo[nt][0] = Xl[r0x * 32 + c];
                blo[nt][1] = Xl[r1x * 32 + c];
            }
            // A fragments: LDS.64 k-pairs, split+pack
            uint32_t ahi[2][4], alo[2][4];
            const int c0 = 16 * kw + 2 * tq;
#pragma unroll
            for (int mf = 0; mf < 2; mf++) {
                int rb = mh * 32 + mf * 16 + g;
                float2 p00 = *(const float2*)(As + rb * APADF + c0);
                float2 p10 = *(const float2*)(As + (rb + 8) * APADF + c0);
                float2 p01 = *(const float2*)(As + rb * APADF + c0 + 8);
                float2 p11 = *(const float2*)(As + (rb + 8) * APADF + c0 + 8);
                bsplit2(p00.x, p00.y, ahi[mf][0], alo[mf][0]);
                bsplit2(p10.x, p10.y, ahi[mf][1], alo[mf][1]);
                bsplit2(p01.x, p01.y, ahi[mf][2], alo[mf][2]);
                bsplit2(p11.x, p11.y, ahi[mf][3], alo[mf][3]);
            }

#pragma unroll
            for (int mf = 0; mf < 2; mf++)
#pragma unroll
                for (int nt = 0; nt < 4; nt++) {
                    mma16(acc[mf][nt][0], acc[mf][nt][1], acc[mf][nt][2], acc[mf][nt][3],
                          ahi[mf][0], ahi[mf][1], ahi[mf][2], ahi[mf][3],
                          bhi[nt][0], bhi[nt][1]);
                    mma16(acc[mf][nt][0], acc[mf][nt][1], acc[mf][nt][2], acc[mf][nt][3],
                          alo[mf][0], alo[mf][1], alo[mf][2], alo[mf][3],
                          bhi[nt][0], bhi[nt][1]);
                    mma16(acc[mf][nt][0], acc[mf][nt][1], acc[mf][nt][2], acc[mf][nt][3],
                          ahi[mf][0], ahi[mf][1], ahi[mf][2], ahi[mf][3],
                          blo[nt][0], blo[nt][1]);
                }
        }
        CP_WAIT0();

        // ---- segment epilogue: 2 k-warp partial planes -> fixed-order sum -> g_Hp[ord] ----
        __syncthreads();
        float* Hp = (float*)sm;                   // 2 * 64 * 33 * 4 = 16896 <= 43008
#pragma unroll
        for (int mf = 0; mf < 2; mf++) {
            int r0 = mh * 32 + mf * 16 + g;
#pragma unroll
            for (int nt = 0; nt < 4; nt++) {
                int cc = nt * 8 + 2 * tq;
                float* Hw = Hp + kw * MTILE * 33;
                Hw[r0 * 33 + cc]           = acc[mf][nt][0];
                Hw[r0 * 33 + cc + 1]       = acc[mf][nt][1];
                Hw[(r0 + 8) * 33 + cc]     = acc[mf][nt][2];
                Hw[(r0 + 8) * 33 + cc + 1] = acc[mf][nt][3];
            }
        }
        __syncthreads();

        if (tid < MTILE && (m0 + tid) < NN) {
            float h[32];
#pragma unroll
            for (int k = 0; k < 32; k++)          // deterministic: kw 0 then 1
                h[k] = Hp[tid * 33 + k] + Hp[MTILE * 33 + tid * 33 + k];
            float4* o = (float4*)(g_Hp[ord] + (m0 + tid) * KO);
#pragma unroll
            for (int n4 = 0; n4 < 8; n4++)
                o[n4] = make_float4(h[n4*4], h[n4*4+1], h[n4*4+2], h[n4*4+3]);
        }
        __syncthreads();   // smem free before next segment's loads

        tau = (uint64_t)mt * KT_PER + T1;
    }
}

// ====== Kernel 2: combine nseg planes, h2 = h @ W, BN partials (deterministic) ======
__global__ __launch_bounds__(128)
void k_combine(const float* __restrict__ W) {
    __shared__ float Ws[32 * 32];
    __shared__ float red[128 * 32];
    const int tid = threadIdx.x;
#pragma unroll
    for (int u = 0; u < 8; u++) Ws[tid + 128 * u] = W[tid + 128 * u];
    __syncthreads();

    const size_t row = (size_t)blockIdx.x * 128 + tid;
    float h2[32];
    if (row < NN) {
        const int mt = (int)(row / MTILE);
        const int bf = cover_b((uint64_t)mt * KT_PER);
        const int bl = cover_b((uint64_t)mt * KT_PER + KT_PER - 1);
        const int nseg = bl - bf + 1;              // <= NPLANE
        float h[32];
        {
            const float4* p = (const float4*)(g_Hp[0] + row * KO);
#pragma unroll
            for (int q = 0; q < 8; q++) {
                float4 a = p[q];
                h[q*4+0] = a.x; h[q*4+1] = a.y; h[q*4+2] = a.z; h[q*4+3] = a.w;
            }
        }
        for (int sgi = 1; sgi < nseg; sgi++) {     // fixed ord order
            const float4* p = (const float4*)(g_Hp[sgi] + row * KO);
#pragma unroll
            for (int q = 0; q < 8; q++) {
                float4 a = p[q];
                h[q*4+0] += a.x; h[q*4+1] += a.y; h[q*4+2] += a.z; h[q*4+3] += a.w;
            }
        }
#pragma unroll
        for (int n = 0; n < 32; n++) {
            float s = 0.f;
#pragma unroll
            for (int k = 0; k < 32; k++) s += h[k] * Ws[k * 32 + n];
            h2[n] = s;
        }
        float4* o = (float4*)(g_H2 + row * KO);
#pragma unroll
        for (int q = 0; q < 8; q++)
            o[q] = make_float4(h2[q*4], h2[q*4+1], h2[q*4+2], h2[q*4+3]);
    } else {
#pragma unroll
        for (int n = 0; n < 32; n++) h2[n] = 0.f;
    }

#pragma unroll
    for (int n = 0; n < 32; n++) red[tid * 32 + n] = h2[n];
    __syncthreads();
    for (int st = 64; st > 0; st >>= 1) {
        if (tid < st) {
#pragma unroll
            for (int n = 0; n < 32; n++)
                red[tid * 32 + n] += red[(tid + st) * 32 + n];
        }
        __syncthreads();
    }
    if (tid < 32) g_part[blockIdx.x * KO + tid] = red[tid];
    __syncthreads();
#pragma unroll
    for (int n = 0; n < 32; n++) red[tid * 32 + n] = h2[n] * h2[n];
    __syncthreads();
    for (int st = 64; st > 0; st >>= 1) {
        if (tid < st) {
#pragma unroll
            for (int n = 0; n < 32; n++)
                red[tid * 32 + n] += red[(tid + st) * 32 + n];
        }
        __syncthreads();
    }
    if (tid < 32) g_psq[blockIdx.x * KO + tid] = red[tid];
}

// ========== Kernel 3: finalize BN stats (R14 version — measured fastest) ==========
__global__ void k_stats(const float* __restrict__ gamma,
                        const float* __restrict__ beta,
                        const float* __restrict__ bias) {
    __shared__ double sred[8][KO];
    __shared__ double qred[8][KO];
    const int c = threadIdx.x & 31;
    const int r = threadIdx.x >> 5;   // 0..7
    double s = 0.0, qq = 0.0;
    for (int bb = r; bb < SBLK; bb += 8) {
        s  += (double)g_part[bb * KO + c];
        qq += (double)g_psq [bb * KO + c];
    }
    sred[r][c] = s; qred[r][c] = qq;
    __syncthreads();
    if (r == 0) {
        double ts = 0.0, tq2 = 0.0;
#pragma unroll
        for (int y = 0; y < 8; y++) { ts += sred[y][c]; tq2 += qred[y][c]; }
        double mean = ts / (double)NN;
        double var  = tq2 / (double)NN - mean * mean;
        double inv  = 1.0 / sqrt(var + 1e-5);
        double gsc  = (double)gamma[c] * inv;
        g_scale[c] = (float)gsc;
        g_shift[c] = (float)((double)beta[c] + (double)bias[c] - mean * gsc);
    }
}

// ========== Kernel 4: out = relu(H2*scale + shift) (R14 version) ==========
__global__ void k_apply(float* __restrict__ out) {
    int idx4 = blockIdx.x * blockDim.x + threadIdx.x;
    float4 h  = *(const float4*)(g_H2 + (size_t)idx4 * 4);
    int cb    = (idx4 * 4) & 31;
    float4 sc = *(const float4*)(g_scale + cb);
    float4 sh = *(const float4*)(g_shift + cb);
    float4 o;
    o.x = fmaxf(h.x * sc.x + sh.x, 0.f);
    o.y = fmaxf(h.y * sc.y + sh.y, 0.f);
    o.z = fmaxf(h.z * sc.z + sh.z, 0.f);
    o.w = fmaxf(h.w * sc.w + sh.w, 0.f);
    *(float4*)(out + (size_t)idx4 * 4) = o;
}

// ================= launch =================
extern "C" void kernel_launch(void* const* d_in, const int* in_sizes, int n_in,
                              void* d_out, int out_size) {
    const float* A     = (const float*)d_in[0];
    const float* X     = (const float*)d_in[1];
    const float* W     = (const float*)d_in[2];
    const float* gamma = (const float*)d_in[3];
    const float* beta  = (const float*)d_in[4];
    const float* bias  = (const float*)d_in[5];
    float* out = (float*)d_out;

    cudaFuncSetAttribute(k_gemm1, cudaFuncAttributeMaxDynamicSharedMemorySize, SMEM_TOTAL);

    k_prep<<<(NN / 2) * KO / 256, 256>>>(X);
    k_gemm1<<<GRIDP, 128, SMEM_TOTAL>>>(A);
    k_combine<<<SBLK, 128>>>(W);
    k_stats<<<1, 256>>>(gamma, beta, bias);
    k_apply<<<(NN * KO / 4) / 256, 256>>>(out);
}